// round 4
// baseline (speedup 1.0000x reference)
#include <cuda_runtime.h>
#include <math.h>

// Problem constants
#define B_    512
#define H_    512
#define OUT_  66
#define NCLS_ 12
#define INW_  78            // OUT_ + NCLS_
#define G4_   2048          // 4*H_
#define LEN_  64
#define BH_   (B_*H_)       // 262144

// Device scratch (no allocations allowed)
// Weight/Z columns are PERMUTED: p = u*4 + gate  (gate order i,f,g,o), u=0..511
__device__ float g_Wt1[H_ * G4_];       // W_hh^T permuted          [K=512][N'=2048]
__device__ float g_Wt2[H_ * G4_];       // (W_hh + Wio@Wfc)^T permuted
__device__ float g_Z0[B_ * G4_];        // step-0 additive term (permuted cols)
__device__ float g_Z [B_ * G4_];        // steps>=1 additive term (permuted cols)
__device__ float g_h0[BH_];
__device__ float g_c [BH_];
__device__ float g_H [LEN_ * BH_];      // all hidden states (64 MB)

// packed f32x2 helpers (sm_100+)
__device__ __forceinline__ void ffma2(unsigned long long& d, unsigned long long a,
                                      unsigned long long b) {
    asm("fma.rn.f32x2 %0, %1, %2, %0;" : "+l"(d) : "l"(a), "l"(b));
}
__device__ __forceinline__ unsigned long long splat2(float x) {
    unsigned long long r;
    asm("mov.b64 %0, {%1, %1};" : "=l"(r) : "f"(x));
    return r;
}
__device__ __forceinline__ unsigned long long pack2(float lo, float hi) {
    unsigned long long r;
    asm("mov.b64 %0, {%1, %2};" : "=l"(r) : "f"(lo), "f"(hi));
    return r;
}
__device__ __forceinline__ float2 unpack2(unsigned long long v) {
    float2 f;
    asm("mov.b64 {%0, %1}, %2;" : "=f"(f.x), "=f"(f.y) : "l"(v));
    return f;
}

// stable fast activations (__expf err ~2 ulp; forms avoid inf/inf)
__device__ __forceinline__ float fsigm(float x) {
    return __frcp_rn(1.0f + __expf(-x));
}
__device__ __forceinline__ float ftanh(float x) {
    return 1.0f - 2.0f * __frcp_rn(1.0f + __expf(2.0f * x));
}

// ---------------------------------------------------------------------------
// h0 = frame0 @ W_inh^T + b_inh ; c0 = frame0 @ W_inc^T + b_inc
// ---------------------------------------------------------------------------
__global__ void k_prep_state(const float* __restrict__ inp,
                             const float* __restrict__ Winh, const float* __restrict__ binh,
                             const float* __restrict__ Winc, const float* __restrict__ binc) {
    int b = blockIdx.x;
    __shared__ float fr[OUT_];
    if (threadIdx.x < OUT_) fr[threadIdx.x] = inp[b * OUT_ + threadIdx.x];
    __syncthreads();
    for (int k = threadIdx.x; k < H_; k += blockDim.x) {
        float sh = binh[k], sc = binc[k];
        const float* wh = Winh + k * OUT_;
        const float* wc = Winc + k * OUT_;
        #pragma unroll 6
        for (int j = 0; j < OUT_; j++) {
            float f = fr[j];
            sh += f * wh[j];
            sc += f * wc[j];
        }
        g_h0[b * H_ + k] = sh;
        g_c [b * H_ + k] = sc;
    }
}

// ---------------------------------------------------------------------------
// Z (permuted columns p = u*4+gate)
// ---------------------------------------------------------------------------
__global__ void k_prep_Z(const float* __restrict__ W_ih,
                         const float* __restrict__ b_ih, const float* __restrict__ b_hh,
                         const float* __restrict__ b_fc,
                         const float* __restrict__ inp, const int* __restrict__ labels) {
    int n  = blockIdx.x * 256 + threadIdx.x;        // original column
    int p  = ((n & 511) << 2) | (n >> 9);           // permuted column
    int bb = blockIdx.y * 8;
    __shared__ float fr[8][OUT_];
    __shared__ float bf[OUT_];
    __shared__ int   lb[8];
    for (int x = threadIdx.x; x < 8 * OUT_; x += 256)
        fr[x / OUT_][x % OUT_] = inp[(bb + x / OUT_) * OUT_ + (x % OUT_)];
    if (threadIdx.x < OUT_) bf[threadIdx.x] = b_fc[threadIdx.x];
    if (threadIdx.x < 8)    lb[threadIdx.x] = labels[bb + threadIdx.x];
    __syncthreads();

    const float* w = W_ih + (size_t)n * INW_;
    float s1 = 0.0f;
    float a[8] = {0, 0, 0, 0, 0, 0, 0, 0};
    #pragma unroll 6
    for (int j = 0; j < OUT_; j++) {
        float wj = w[j];
        s1 += bf[j] * wj;
        #pragma unroll
        for (int i = 0; i < 8; i++) a[i] += fr[i][j] * wj;
    }
    float base = b_ih[n] + b_hh[n];
    #pragma unroll
    for (int i = 0; i < 8; i++) {
        int b = bb + i;
        float cls = w[OUT_ + lb[i]];
        g_Z0[(size_t)b * G4_ + p] = base + cls + a[i];
        g_Z [(size_t)b * G4_ + p] = base + cls + s1;
    }
}

// ---------------------------------------------------------------------------
// Wt1[k,p(n)] = W_hh[n,k] ; Wt2[k,p(n)] = W_hh[n,k] + sum_j W_ih[n,j]*W_fc[j,k]
// ---------------------------------------------------------------------------
__global__ void k_prep_W(const float* __restrict__ W_ih,
                         const float* __restrict__ W_hh,
                         const float* __restrict__ W_fc) {
    int n  = blockIdx.x * 256 + threadIdx.x;
    int p  = ((n & 511) << 2) | (n >> 9);
    int k0 = blockIdx.y * 8;
    __shared__ float wf[OUT_][8];
    for (int x = threadIdx.x; x < OUT_ * 8; x += 256)
        wf[x / 8][x % 8] = W_fc[(size_t)(x / 8) * H_ + k0 + (x % 8)];
    __syncthreads();

    const float* w = W_ih + (size_t)n * INW_;
    float a[8] = {0, 0, 0, 0, 0, 0, 0, 0};
    #pragma unroll 6
    for (int j = 0; j < OUT_; j++) {
        float wj = w[j];
        #pragma unroll
        for (int i = 0; i < 8; i++) a[i] += wj * wf[j][i];
    }
    #pragma unroll
    for (int i = 0; i < 8; i++) {
        int k = k0 + i;
        float whh = W_hh[(size_t)n * H_ + k];
        g_Wt1[(size_t)k * G4_ + p] = whh;
        g_Wt2[(size_t)k * G4_ + p] = whh + a[i];
    }
}

// ---------------------------------------------------------------------------
// Fused step: gates = Hin @ Wt + Z (permuted cols), then LSTM pointwise.
// BM=64, BN=64(16u x 4gates), BK=16; 128 threads; thread tile 8m x 4n.
// Gate-pairs packed in f32x2 lanes: B pairs come free from float4 LDS;
// A is PRE-SPLATTED into smem (u64 {a,a}) at staging time.
// Per kk per thread: 4 LDS.128 (A-splats) + 1 LDS.128 (B) + 16 FFMA2.
// grid (32, 8) = 256 CTAs -> 2 CTAs/SM.
// ---------------------------------------------------------------------------
__global__ __launch_bounds__(128) void k_step(int t) {
    const float* __restrict__ Hin = (t == 0) ? g_h0 : g_H + (size_t)(t - 1) * BH_;
    const float* __restrict__ W   = (t == 0) ? g_Wt1 : g_Wt2;
    const float* __restrict__ Z   = (t == 0) ? g_Z0  : g_Z;

    __shared__ __align__(16) unsigned long long Asp[2][16][64];  // splatted Hin [k][m]
    __shared__ __align__(16) float              Bs [2][16][64];  // W slab [k][n]

    int tid = threadIdx.x;
    int tx = tid & 15;              // n dir: 4 gate-cols (one u)
    int ty = tid >> 4;              // m dir: 8 rows each (0..7)
    int n0 = blockIdx.x * 64;
    int m0 = blockIdx.y * 64;

    // staging indices
    int am = tid >> 1;              // 64 m rows, 2 threads each
    int ak = (tid & 1) << 3;        // 8 k's per thread
    int br = tid >> 3;              // 16 k rows, 8 threads each
    int bc = (tid & 7) << 3;        // 8 n's per thread

    // acc[gp][m]: gp=0 -> (i,f) pair, gp=1 -> (g,o) pair; m = 0..7
    unsigned long long acc[2][8];
    {
        const float* zp = Z + (size_t)(m0 + ty * 8) * G4_ + n0 + tx * 4;
        #pragma unroll
        for (int m = 0; m < 8; m++) {
            float4 z = *(const float4*)(zp + (size_t)m * G4_);
            acc[0][m] = pack2(z.x, z.y);
            acc[1][m] = pack2(z.z, z.w);
        }
    }

    const float* aptr = Hin + (size_t)(m0 + am) * H_ + ak;
    const float* bptr = W + (size_t)br * G4_ + n0 + bc;

    float4 av0 = *(const float4*)(aptr);
    float4 av1 = *(const float4*)(aptr + 4);
    float4 bv0 = *(const float4*)(bptr);
    float4 bv1 = *(const float4*)(bptr + 4);

    // stage slab 0
    Asp[0][ak + 0][am] = splat2(av0.x);
    Asp[0][ak + 1][am] = splat2(av0.y);
    Asp[0][ak + 2][am] = splat2(av0.z);
    Asp[0][ak + 3][am] = splat2(av0.w);
    Asp[0][ak + 4][am] = splat2(av1.x);
    Asp[0][ak + 5][am] = splat2(av1.y);
    Asp[0][ak + 6][am] = splat2(av1.z);
    Asp[0][ak + 7][am] = splat2(av1.w);
    *(float4*)&Bs[0][br][bc]     = bv0;
    *(float4*)&Bs[0][br][bc + 4] = bv1;
    __syncthreads();

    #pragma unroll 2
    for (int i = 0; i < 32; i++) {
        int s = i & 1;
        if (i < 31) {
            av0 = *(const float4*)(aptr + (i + 1) * 16);
            av1 = *(const float4*)(aptr + (i + 1) * 16 + 4);
            bv0 = *(const float4*)(bptr + (size_t)(i + 1) * 16 * G4_);
            bv1 = *(const float4*)(bptr + (size_t)(i + 1) * 16 * G4_ + 4);
        }
        #pragma unroll
        for (int kk = 0; kk < 16; kk++) {
            const ulonglong2* ar = (const ulonglong2*)&Asp[s][kk][ty << 3];
            ulonglong2 a01 = ar[0];
            ulonglong2 a23 = ar[1];
            ulonglong2 a45 = ar[2];
            ulonglong2 a67 = ar[3];
            ulonglong2 bb = *(const ulonglong2*)&Bs[s][kk][tx << 2]; // (b_i,b_f),(b_g,b_o)
            ffma2(acc[0][0], a01.x, bb.x); ffma2(acc[1][0], a01.x, bb.y);
            ffma2(acc[0][1], a01.y, bb.x); ffma2(acc[1][1], a01.y, bb.y);
            ffma2(acc[0][2], a23.x, bb.x); ffma2(acc[1][2], a23.x, bb.y);
            ffma2(acc[0][3], a23.y, bb.x); ffma2(acc[1][3], a23.y, bb.y);
            ffma2(acc[0][4], a45.x, bb.x); ffma2(acc[1][4], a45.x, bb.y);
            ffma2(acc[0][5], a45.y, bb.x); ffma2(acc[1][5], a45.y, bb.y);
            ffma2(acc[0][6], a67.x, bb.x); ffma2(acc[1][6], a67.x, bb.y);
            ffma2(acc[0][7], a67.y, bb.x); ffma2(acc[1][7], a67.y, bb.y);
        }
        if (i < 31) {
            int d = s ^ 1;
            Asp[d][ak + 0][am] = splat2(av0.x);
            Asp[d][ak + 1][am] = splat2(av0.y);
            Asp[d][ak + 2][am] = splat2(av0.z);
            Asp[d][ak + 3][am] = splat2(av0.w);
            Asp[d][ak + 4][am] = splat2(av1.x);
            Asp[d][ak + 5][am] = splat2(av1.y);
            Asp[d][ak + 6][am] = splat2(av1.z);
            Asp[d][ak + 7][am] = splat2(av1.w);
            *(float4*)&Bs[d][br][bc]     = bv0;
            *(float4*)&Bs[d][br][bc + 4] = bv1;
        }
        __syncthreads();
    }

    // Fused LSTM pointwise epilogue
    int u = (blockIdx.x << 4) + tx;
    float* hout = g_H + (size_t)t * BH_;
    #pragma unroll
    for (int m = 0; m < 8; m++) {
        float2 g_if = unpack2(acc[0][m]);   // (i, f)
        float2 g_go = unpack2(acc[1][m]);   // (g, o)
        int b = m0 + ty * 8 + m;
        int idx = b * H_ + u;
        float c  = g_c[idx];
        float cn = fsigm(g_if.y) * c + fsigm(g_if.x) * ftanh(g_go.x);
        float hn = fsigm(g_go.y) * ftanh(cn);
        g_c[idx] = cn;
        hout[idx] = hn;
    }
}

// ---------------------------------------------------------------------------
// Final: out[b,t,:] = g_H[t,b,:] @ W_fc^T + b_fc.   Warp per (t,b) row.
// ---------------------------------------------------------------------------
__global__ __launch_bounds__(256) void k_fc(float* __restrict__ out,
                                            const float* __restrict__ W_fc,
                                            const float* __restrict__ b_fc) {
    __shared__ float hs[8][H_];
    int w = threadIdx.x >> 5;
    int lane = threadIdx.x & 31;
    int r = blockIdx.x * 8 + w;                 // r = t*512 + b
    const float4* hrow = (const float4*)(g_H + (size_t)r * H_);
    float4* dst = (float4*)hs[w];
    #pragma unroll
    for (int x = lane; x < H_ / 4; x += 32) dst[x] = hrow[x];
    __syncwarp();

    int t = r >> 9;
    int b = r & 511;
    float* orow = out + ((size_t)b * LEN_ + t) * OUT_;
    const float4* hv = (const float4*)hs[w];
    for (int j = lane; j < OUT_; j += 32) {
        const float4* wrow = (const float4*)(W_fc + (size_t)j * H_);
        float s = 0.0f;
        #pragma unroll 8
        for (int x = 0; x < H_ / 4; x++) {
            float4 a = hv[x];
            float4 c = wrow[x];
            s += a.x * c.x + a.y * c.y + a.z * c.z + a.w * c.w;
        }
        orow[j] = s + b_fc[j];
    }
}

// ---------------------------------------------------------------------------
extern "C" void kernel_launch(void* const* d_in, const int* in_sizes, int n_in,
                              void* d_out, int out_size) {
    int off = (n_in >= 13) ? 1 : 0;   // 'length' scalar present
    const float* inputs = (const float*)d_in[0];
    const int*   labels = (const int*)  d_in[1];
    const float* W_ih  = (const float*)d_in[2 + off];
    const float* W_hh  = (const float*)d_in[3 + off];
    const float* b_ih  = (const float*)d_in[4 + off];
    const float* b_hh  = (const float*)d_in[5 + off];
    const float* W_fc  = (const float*)d_in[6 + off];
    const float* b_fc  = (const float*)d_in[7 + off];
    const float* W_inh = (const float*)d_in[8 + off];
    const float* b_inh = (const float*)d_in[9 + off];
    const float* W_inc = (const float*)d_in[10 + off];
    const float* b_inc = (const float*)d_in[11 + off];
    float* out = (float*)d_out;

    k_prep_state<<<B_, 256>>>(inputs, W_inh, b_inh, W_inc, b_inc);
    k_prep_Z<<<dim3(8, 64), 256>>>(W_ih, b_ih, b_hh, b_fc, inputs, labels);
    k_prep_W<<<dim3(8, 64), 256>>>(W_ih, W_hh, W_fc);

    for (int t = 0; t < LEN_; t++) {
        k_step<<<dim3(32, 8), 128>>>(t);
    }

    k_fc<<<(LEN_ * B_) / 8, 256>>>(out, W_fc, b_fc);
}

// round 6
// speedup vs baseline: 1.2091x; 1.2091x over previous
#include <cuda_runtime.h>
#include <cuda_bf16.h>
#include <math.h>
#include <stdint.h>

// Problem constants
#define B_    512
#define H_    512
#define OUT_  66
#define NCLS_ 12
#define INW_  78
#define G4_   2048          // 4*H_
#define LEN_  64
#define BH_   (B_*H_)

// Device scratch (static globals; no runtime allocation)
__device__ float g_Z0[B_ * G4_];            // step-0 additive term (permuted cols)
__device__ float g_Z [B_ * G4_];            // steps>=1 additive term (permuted cols)
__device__ float g_c [BH_];                 // cell state fp32 [b][u]
__device__ __nv_bfloat16 g_W1hi[G4_ * H_];  // W_hh split, rows permuted  [p][k]
__device__ __nv_bfloat16 g_W1lo[G4_ * H_];
__device__ __nv_bfloat16 g_W2hi[G4_ * H_];  // (W_hh + Wio@Wfc) split     [p][k]
__device__ __nv_bfloat16 g_W2lo[G4_ * H_];
__device__ __nv_bfloat16 g_h0hi[BH_];
__device__ __nv_bfloat16 g_h0lo[BH_];
__device__ __nv_bfloat16 g_Hhi[LEN_ * BH_]; // per-step hidden splits [t][b][u]
__device__ __nv_bfloat16 g_Hlo[LEN_ * BH_];

__device__ __forceinline__ float fsigm(float x) { return __frcp_rn(1.0f + __expf(-x)); }
__device__ __forceinline__ float ftanh(float x) { return 1.0f - 2.0f * __frcp_rn(1.0f + __expf(2.0f * x)); }

__device__ __forceinline__ uint32_t smem_u32(const void* p) {
    uint32_t a;
    asm("{ .reg .u64 t; cvta.to.shared.u64 t, %1; cvt.u32.u64 %0, t; }" : "=r"(a) : "l"(p));
    return a;
}
__device__ __forceinline__ void ldsm_x4(uint32_t& r0, uint32_t& r1, uint32_t& r2, uint32_t& r3,
                                        uint32_t addr) {
    asm volatile("ldmatrix.sync.aligned.m8n8.x4.shared.b16 {%0,%1,%2,%3}, [%4];"
                 : "=r"(r0), "=r"(r1), "=r"(r2), "=r"(r3) : "r"(addr));
}
__device__ __forceinline__ void mma16816(float& c0, float& c1, float& c2, float& c3,
                                         uint32_t a0, uint32_t a1, uint32_t a2, uint32_t a3,
                                         uint32_t b0, uint32_t b1) {
    asm volatile(
        "mma.sync.aligned.m16n8k16.row.col.f32.bf16.bf16.f32 "
        "{%0,%1,%2,%3}, {%4,%5,%6,%7}, {%8,%9}, {%0,%1,%2,%3};"
        : "+f"(c0), "+f"(c1), "+f"(c2), "+f"(c3)
        : "r"(a0), "r"(a1), "r"(a2), "r"(a3), "r"(b0), "r"(b1));
}

// ---------------------------------------------------------------------------
// h0 = frame0 @ W_inh^T + b_inh (bf16-split) ; c0 = frame0 @ W_inc^T + b_inc
// ---------------------------------------------------------------------------
__global__ void k_prep_state(const float* __restrict__ inp,
                             const float* __restrict__ Winh, const float* __restrict__ binh,
                             const float* __restrict__ Winc, const float* __restrict__ binc) {
    int b = blockIdx.x;
    __shared__ float fr[OUT_];
    if (threadIdx.x < OUT_) fr[threadIdx.x] = inp[b * OUT_ + threadIdx.x];
    __syncthreads();
    for (int k = threadIdx.x; k < H_; k += blockDim.x) {
        float sh = binh[k], sc = binc[k];
        const float* wh = Winh + k * OUT_;
        const float* wc = Winc + k * OUT_;
        #pragma unroll 6
        for (int j = 0; j < OUT_; j++) {
            float f = fr[j];
            sh += f * wh[j];
            sc += f * wc[j];
        }
        __nv_bfloat16 hi = __float2bfloat16_rn(sh);
        g_h0hi[b * H_ + k] = hi;
        g_h0lo[b * H_ + k] = __float2bfloat16_rn(sh - __bfloat162float(hi));
        g_c[b * H_ + k] = sc;
    }
}

// ---------------------------------------------------------------------------
// Z (permuted columns p = u*4+gate)
// ---------------------------------------------------------------------------
__global__ void k_prep_Z(const float* __restrict__ W_ih,
                         const float* __restrict__ b_ih, const float* __restrict__ b_hh,
                         const float* __restrict__ b_fc,
                         const float* __restrict__ inp, const int* __restrict__ labels) {
    int n  = blockIdx.x * 256 + threadIdx.x;
    int p  = ((n & 511) << 2) | (n >> 9);
    int bb = blockIdx.y * 8;
    __shared__ float fr[8][OUT_];
    __shared__ float bf[OUT_];
    __shared__ int   lb[8];
    for (int x = threadIdx.x; x < 8 * OUT_; x += 256)
        fr[x / OUT_][x % OUT_] = inp[(bb + x / OUT_) * OUT_ + (x % OUT_)];
    if (threadIdx.x < OUT_) bf[threadIdx.x] = b_fc[threadIdx.x];
    if (threadIdx.x < 8)    lb[threadIdx.x] = labels[bb + threadIdx.x];
    __syncthreads();

    const float* w = W_ih + (size_t)n * INW_;
    float s1 = 0.0f;
    float a[8] = {0, 0, 0, 0, 0, 0, 0, 0};
    #pragma unroll 6
    for (int j = 0; j < OUT_; j++) {
        float wj = w[j];
        s1 += bf[j] * wj;
        #pragma unroll
        for (int i = 0; i < 8; i++) a[i] += fr[i][j] * wj;
    }
    float base = b_ih[n] + b_hh[n];
    #pragma unroll
    for (int i = 0; i < 8; i++) {
        int b = bb + i;
        float cls = w[OUT_ + lb[i]];
        g_Z0[(size_t)b * G4_ + p] = base + cls + a[i];
        g_Z [(size_t)b * G4_ + p] = base + cls + s1;
    }
}

// ---------------------------------------------------------------------------
// W splits, row-permuted, row-major [p][k]:
// W1 = W_hh ; W2 = W_hh + W_ih[:, :66] @ W_fc
// ---------------------------------------------------------------------------
__global__ void k_prep_W(const float* __restrict__ W_ih,
                         const float* __restrict__ W_hh,
                         const float* __restrict__ W_fc) {
    int n  = blockIdx.x * 256 + threadIdx.x;
    int p  = ((n & 511) << 2) | (n >> 9);
    int k0 = blockIdx.y * 8;
    __shared__ float wf[OUT_][8];
    for (int x = threadIdx.x; x < OUT_ * 8; x += 256)
        wf[x / 8][x % 8] = W_fc[(size_t)(x / 8) * H_ + k0 + (x % 8)];
    __syncthreads();

    const float* w = W_ih + (size_t)n * INW_;
    float a[8] = {0, 0, 0, 0, 0, 0, 0, 0};
    #pragma unroll 6
    for (int j = 0; j < OUT_; j++) {
        float wj = w[j];
        #pragma unroll
        for (int i = 0; i < 8; i++) a[i] += wj * wf[j][i];
    }
    #pragma unroll
    for (int i = 0; i < 8; i++) {
        int k = k0 + i;
        float w1 = W_hh[(size_t)n * H_ + k];
        float w2 = w1 + a[i];
        __nv_bfloat16 h1 = __float2bfloat16_rn(w1);
        __nv_bfloat16 h2 = __float2bfloat16_rn(w2);
        size_t o = (size_t)p * H_ + k;
        g_W1hi[o] = h1;
        g_W1lo[o] = __float2bfloat16_rn(w1 - __bfloat162float(h1));
        g_W2hi[o] = h2;
        g_W2lo[o] = __float2bfloat16_rn(w2 - __bfloat162float(h2));
    }
}

// ---------------------------------------------------------------------------
// HMMA fused step. CTA tile 64(m:batch) x 64(n:permuted gate cols), BK=64,
// 4 warps 2x2 (warp tile 32x32), mma.m16n8k16 bf16, 3 error-split passes.
// Fused LSTM pointwise epilogue (shfl-pair gate exchange).
// grid (32 n, 8 m) = 256 CTAs, 128 threads.
// ---------------------------------------------------------------------------
__global__ __launch_bounds__(128) void k_step_mma(int t) {
    __shared__ __align__(16) char smA[2][8192];   // 64 rows x 128B, xor-swizzled
    __shared__ __align__(16) char smB[2][8192];

    const __nv_bfloat16* __restrict__ Ahi = (t == 0) ? g_h0hi : g_Hhi + (size_t)(t - 1) * BH_;
    const __nv_bfloat16* __restrict__ Alo = (t == 0) ? g_h0lo : g_Hlo + (size_t)(t - 1) * BH_;
    const __nv_bfloat16* __restrict__ Bhi = (t == 0) ? g_W1hi : g_W2hi;
    const __nv_bfloat16* __restrict__ Blo = (t == 0) ? g_W1lo : g_W2lo;
    const float* __restrict__ Zp = (t == 0) ? g_Z0 : g_Z;

    int tid  = threadIdx.x;
    int lane = tid & 31;
    int wid  = tid >> 5;
    int wr   = wid >> 1;          // warp m (2)
    int wc   = wid & 1;           // warp n (2)
    int n0   = blockIdx.x * 64;   // permuted col tile
    int m0   = blockIdx.y * 64;   // batch tile
    int u0   = n0 >> 2;

    // staging: thread -> (row, half-row of 64B)
    int arow  = tid >> 1;
    int ahalf = tid & 1;
    uint32_t swbase = (uint32_t)(arow & 7);

    float acc[2][4][4];           // [m16 block][n8 block][frag]
    #pragma unroll
    for (int i = 0; i < 2; i++)
        #pragma unroll
        for (int j = 0; j < 4; j++)
            #pragma unroll
            for (int q = 0; q < 4; q++) acc[i][j][q] = 0.0f;

    // ldmatrix base addresses (per warp)
    uint32_t sA0 = smem_u32(smA[0]);
    uint32_t sB0 = smem_u32(smB[0]);
    int lrowA = wr * 32 + (lane & 15);            // + mb*16
    int lrowB = wc * 32 + (lane & 15);            // + nb2*16
    int lchunk = lane >> 4;                        // 0/1 -> k8 half

    uint4 ra[4], rb[4];
    // prefetch + store stage 0
    {
        const uint4* ap = (const uint4*)(Ahi + (size_t)(m0 + arow) * H_ + ahalf * 32);
        const uint4* bp = (const uint4*)(Bhi + (size_t)(n0 + arow) * H_ + ahalf * 32);
        #pragma unroll
        for (int j = 0; j < 4; j++) { ra[j] = ap[j]; rb[j] = bp[j]; }
        char* da = smA[0] + arow * 128;
        char* db = smB[0] + arow * 128;
        #pragma unroll
        for (int j = 0; j < 4; j++) {
            uint32_t off = (uint32_t)(((ahalf * 4 + j) ^ swbase) << 4);
            *(uint4*)(da + off) = ra[j];
            *(uint4*)(db + off) = rb[j];
        }
    }
    __syncthreads();

    #pragma unroll 1
    for (int it = 0; it < 24; it++) {
        int cur = it & 1;
        // prefetch next stage
        if (it < 23) {
            int nit = it + 1;
            int seg = nit >> 3, kb = nit & 7;
            const __nv_bfloat16* As = (seg == 1) ? Alo : Ahi;
            const __nv_bfloat16* Bs = (seg == 2) ? Blo : Bhi;
            const uint4* ap = (const uint4*)(As + (size_t)(m0 + arow) * H_ + kb * 64 + ahalf * 32);
            const uint4* bp = (const uint4*)(Bs + (size_t)(n0 + arow) * H_ + kb * 64 + ahalf * 32);
            #pragma unroll
            for (int j = 0; j < 4; j++) { ra[j] = ap[j]; rb[j] = bp[j]; }
        }
        // compute 4 k16 chunks from buffer cur
        uint32_t aBase = sA0 + (uint32_t)cur * 8192;
        uint32_t bBase = sB0 + (uint32_t)cur * 8192;
        #pragma unroll
        for (int kc = 0; kc < 4; kc++) {
            uint32_t a[2][4], b[2][4];
            #pragma unroll
            for (int mb = 0; mb < 2; mb++) {
                int row = lrowA + mb * 16;
                uint32_t off = (uint32_t)row * 128u
                             + (uint32_t)(((2 * kc + lchunk) ^ (row & 7)) << 4);
                ldsm_x4(a[mb][0], a[mb][1], a[mb][2], a[mb][3], aBase + off);
            }
            #pragma unroll
            for (int nb2 = 0; nb2 < 2; nb2++) {
                int row = lrowB + nb2 * 16;
                uint32_t off = (uint32_t)row * 128u
                             + (uint32_t)(((2 * kc + lchunk) ^ (row & 7)) << 4);
                ldsm_x4(b[nb2][0], b[nb2][1], b[nb2][2], b[nb2][3], bBase + off);
            }
            #pragma unroll
            for (int mb = 0; mb < 2; mb++)
                #pragma unroll
                for (int j = 0; j < 4; j++) {
                    int nb2 = j >> 1, par = j & 1;
                    mma16816(acc[mb][j][0], acc[mb][j][1], acc[mb][j][2], acc[mb][j][3],
                             a[mb][0], a[mb][1], a[mb][2], a[mb][3],
                             b[nb2][par], b[nb2][par + 2]);
                }
        }
        // store next stage
        if (it < 23) {
            int nxt = cur ^ 1;
            char* da = smA[nxt] + arow * 128;
            char* db = smB[nxt] + arow * 128;
            #pragma unroll
            for (int j = 0; j < 4; j++) {
                uint32_t off = (uint32_t)(((ahalf * 4 + j) ^ swbase) << 4);
                *(uint4*)(da + off) = ra[j];
                *(uint4*)(db + off) = rb[j];
            }
        }
        __syncthreads();
    }

    // -------- fused LSTM epilogue --------
    bool even = (lane & 1) == 0;
    float* hout_base = (float*)nullptr; (void)hout_base;
    size_t toff = (size_t)t * BH_;
    #pragma unroll
    for (int mb = 0; mb < 2; mb++) {
        #pragma unroll
        for (int j = 0; j < 4; j++) {
            float d0 = acc[mb][j][0], d1 = acc[mb][j][1];
            float d2 = acc[mb][j][2], d3 = acc[mb][j][3];
            float x = __shfl_xor_sync(0xffffffffu, even ? d2 : d0, 1);
            float y = __shfl_xor_sync(0xffffffffu, even ? d3 : d1, 1);
            int r   = wr * 32 + mb * 16 + (lane >> 2) + (even ? 0 : 8);
            int ugl = wc * 8 + j * 2 + ((lane & 3) >> 1);
            float gi = even ? d0 : x;
            float gf = even ? d1 : y;
            float gg = even ? x : d2;
            float go = even ? y : d3;
            const float4 z = *(const float4*)(Zp + (size_t)(m0 + r) * G4_ + n0 + ugl * 4);
            gi += z.x; gf += z.y; gg += z.z; go += z.w;
            int ci = (m0 + r) * H_ + u0 + ugl;
            float c  = g_c[ci];
            float cn = fsigm(gf) * c + fsigm(gi) * ftanh(gg);
            float hn = fsigm(go) * ftanh(cn);
            g_c[ci] = cn;
            __nv_bfloat16 hi = __float2bfloat16_rn(hn);
            g_Hhi[toff + ci] = hi;
            g_Hlo[toff + ci] = __float2bfloat16_rn(hn - __bfloat162float(hi));
        }
    }
}

// ---------------------------------------------------------------------------
// Final: out[b,t,:] = (h_hi+h_lo)[t,b,:] @ W_fc^T + b_fc.  Warp per (t,b) row.
// ---------------------------------------------------------------------------
__global__ __launch_bounds__(256) void k_fc(float* __restrict__ out,
                                            const float* __restrict__ W_fc,
                                            const float* __restrict__ b_fc) {
    __shared__ float hs[8][H_];
    int w = threadIdx.x >> 5;
    int lane = threadIdx.x & 31;
    int r = blockIdx.x * 8 + w;                 // r = t*512 + b
    const uint4* hr = (const uint4*)(g_Hhi + (size_t)r * H_);
    const uint4* lr = (const uint4*)(g_Hlo + (size_t)r * H_);
    for (int x = lane; x < H_ / 8; x += 32) {
        uint4 a = hr[x], b = lr[x];
        const __nv_bfloat162* ap = (const __nv_bfloat162*)&a;
        const __nv_bfloat162* bp = (const __nv_bfloat162*)&b;
        float* d = &hs[w][x * 8];
        #pragma unroll
        for (int e = 0; e < 4; e++) {
            float2 fa = __bfloat1622float2(ap[e]);
            float2 fb = __bfloat1622float2(bp[e]);
            d[2 * e]     = fa.x + fb.x;
            d[2 * e + 1] = fa.y + fb.y;
        }
    }
    __syncwarp();

    int t = r >> 9;
    int b = r & 511;
    float* orow = out + ((size_t)b * LEN_ + t) * OUT_;
    const float4* hv = (const float4*)hs[w];
    for (int j = lane; j < OUT_; j += 32) {
        const float4* wrow = (const float4*)(W_fc + (size_t)j * H_);
        float s = 0.0f;
        #pragma unroll 8
        for (int x = 0; x < H_ / 4; x++) {
            float4 a = hv[x];
            float4 c = wrow[x];
            s += a.x * c.x + a.y * c.y + a.z * c.z + a.w * c.w;
        }
        orow[j] = s + b_fc[j];
    }
}

// ---------------------------------------------------------------------------
extern "C" void kernel_launch(void* const* d_in, const int* in_sizes, int n_in,
                              void* d_out, int out_size) {
    int off = (n_in >= 13) ? 1 : 0;   // 'length' scalar present
    const float* inputs = (const float*)d_in[0];
    const int*   labels = (const int*)  d_in[1];
    const float* W_ih  = (const float*)d_in[2 + off];
    const float* W_hh  = (const float*)d_in[3 + off];
    const float* b_ih  = (const float*)d_in[4 + off];
    const float* b_hh  = (const float*)d_in[5 + off];
    const float* W_fc  = (const float*)d_in[6 + off];
    const float* b_fc  = (const float*)d_in[7 + off];
    const float* W_inh = (const float*)d_in[8 + off];
    const float* b_inh = (const float*)d_in[9 + off];
    const float* W_inc = (const float*)d_in[10 + off];
    const float* b_inc = (const float*)d_in[11 + off];
    float* out = (float*)d_out;

    k_prep_state<<<B_, 256>>>(inputs, W_inh, b_inh, W_inc, b_inc);
    k_prep_Z<<<dim3(8, 64), 256>>>(W_ih, b_ih, b_hh, b_fc, inputs, labels);
    k_prep_W<<<dim3(8, 64), 256>>>(W_ih, W_hh, W_fc);

    for (int t = 0; t < LEN_; t++) {
        k_step_mma<<<dim3(32, 8), 128>>>(t);
    }

    k_fc<<<(LEN_ * B_) / 8, 256>>>(out, W_fc, b_fc);
}